// round 2
// baseline (speedup 1.0000x reference)
#include <cuda_runtime.h>
#include <cstdint>

// Problem constants
#define MROWS   65536
#define KDIM    48          // s_in = 32 + 16
#define NSPL    32          // spline groups per row
#define NB      33          // 2K+1 outputs per group (17 heights, 16 widths)
#define NPAD    34          // padded group width (even, for LDS.64)
#define NGRP    8           // spline groups per block
#define BM      128         // rows per block
#define TM      2           // rows per thread
#define THREADS 512         // (BM/TM) * NGRP
#define WS_STRIDE (NGRP * NPAD)                 // 272 floats per k-row
#define AS_STRIDE 52                            // padded A row (mult of 4, conflict-free)
#define SMEM_FLOATS (KDIM * WS_STRIDE + BM * AS_STRIDE + WS_STRIDE)
#define SMEM_BYTES  (SMEM_FLOATS * 4)           // 79936 B

// ---------- packed f32x2 helpers ----------
__device__ __forceinline__ unsigned long long pack2(float a) {
    unsigned long long r;
    asm("mov.b64 %0, {%1, %1};" : "=l"(r) : "f"(a));
    return r;
}
__device__ __forceinline__ void ffma2(unsigned long long& d,
                                      unsigned long long a,
                                      unsigned long long b) {
    asm("fma.rn.f32x2 %0, %1, %2, %0;" : "+l"(d) : "l"(a), "l"(b));
}

// ---------- quadratic spline (per (m,n) pair) ----------
// y[0..16] = unnormalized heights, y[17..32] = unnormalized widths
__device__ __forceinline__ float spline_eval(const unsigned long long acc[17],
                                             float input, float& x_out) {
    float y[34];
#pragma unroll
    for (int p = 0; p < 17; p++) {
        unsigned int lo = (unsigned int)acc[p];
        unsigned int hi = (unsigned int)(acc[p] >> 32);
        y[2 * p]     = __uint_as_float(lo);
        y[2 * p + 1] = __uint_as_float(hi);
    }

    // h = softplus(uh) + 0.001  (robust softplus, matches jax.nn.softplus)
    float h[17];
#pragma unroll
    for (int i = 0; i < 17; i++) {
        float x = y[i];
        h[i] = fmaxf(x, 0.0f) + log1pf(expf(-fabsf(x))) + 0.001f;
    }

    // widths = MIN_BW + (1 - 16*MIN_BW) * softmax(uw)
    float w[16];
    float esum = 0.0f;
#pragma unroll
    for (int i = 0; i < 16; i++) { w[i] = expf(y[17 + i]); esum += w[i]; }
    float inv = 1.0f / esum;
#pragma unroll
    for (int i = 0; i < 16; i++) w[i] = 0.001f + 0.984f * (w[i] * inv);

    // area & normalized heights
    float area = 0.0f;
#pragma unroll
    for (int i = 0; i < 16; i++) area += (h[i] + h[i + 1]) * 0.5f * w[i];
    float hs = 0.999f / area;   // (1 - MIN_BH)/area
#pragma unroll
    for (int i = 0; i < 17; i++) h[i] = 0.001f + h[i] * hs;

    // sequential scan: locations / left-cdf cumsums + predicated bin select.
    // bin_locations[i] = sum_{j<i} w_j (i<=15); index 16 forced to 1+eps > input.
    float L = 0.0f, C = 0.0f;
    float bl = 0.0f, bw = w[0], lcdf = 0.0f, hl = h[0], hr = h[1];
#pragma unroll
    for (int i = 1; i <= 15; i++) {
        L += w[i - 1];
        C += 0.5f * (h[i - 1] + h[i]) * w[i - 1];
        if (input >= L) { bl = L; bw = w[i]; lcdf = C; hl = h[i]; hr = h[i + 1]; }
    }

    float aq    = 0.5f * (hr - hl) * bw;
    float bq    = hl * bw;
    float alpha = (input - bl) / bw;
    float o = aq * alpha * alpha + bq * alpha + lcdf;
    x_out = fminf(fmaxf(o, 0.0f), 1.0f);
    return logf(alpha * (hr - hl) + hl);
}

// ---------- prep: copy z2 into x[:, :32], zero log_det ----------
__global__ void prep_kernel(const float* __restrict__ z, float* __restrict__ out) {
    int tid = blockIdx.x * blockDim.x + threadIdx.x;
    const int NC = MROWS * 8;                  // float4 copies for x[:, :32]
    if (tid < NC) {
        int m = tid >> 3, q = tid & 7;
        ((float4*)out)[(size_t)m * 16 + q] = ((const float4*)z)[(size_t)m * 16 + 8 + q];
    } else {
        int u = tid - NC;
        if (u < MROWS / 4) {
            ((float4*)(out + (size_t)MROWS * 64))[u] = make_float4(0.f, 0.f, 0.f, 0.f);
        }
    }
}

// ---------- fused GEMM + spline ----------
__global__ void __launch_bounds__(THREADS, 1)
spline_main_kernel(const float* __restrict__ c, const float* __restrict__ z,
                   const float* __restrict__ W, const float* __restrict__ b,
                   float* __restrict__ out) {
    extern __shared__ float sm[];
    float* Ws = sm;                                   // [48][272]  W slice (padded)
    float* As = sm + KDIM * WS_STRIDE;                // [128][52]  A tile
    float* bs = As + BM * AS_STRIDE;                  // [272]      bias slice

    const int t       = threadIdx.x;
    const int g       = blockIdx.x;                   // n-group (0..3)
    const int rowbase = blockIdx.y * BM;

    // W slice: cols [g*264, g*264+264), laid out Ws[k*272 + ln*34 + j]
    for (int idx = t; idx < KDIM * (NGRP * NB); idx += THREADS) {
        int k  = idx / (NGRP * NB);
        int cc = idx - k * (NGRP * NB);
        int ln = cc / NB;
        int j  = cc - ln * NB;
        Ws[k * WS_STRIDE + ln * NPAD + j] = W[(size_t)k * 1056 + g * (NGRP * NB) + cc];
    }
    for (int idx = t; idx < KDIM * NGRP; idx += THREADS) {  // zero pad column j=33
        int k = idx >> 3, ln = idx & 7;
        Ws[k * WS_STRIDE + ln * NPAD + 33] = 0.0f;
    }
    if (t < WS_STRIDE) {                                    // bias (padded)
        int ln = t / NPAD, j = t - ln * NPAD;
        bs[t] = (j < NB) ? b[g * (NGRP * NB) + ln * NB + j] : 0.0f;
    }
    // A tile: z2 part (cols 0..31 of A = z[:,32:64])
    for (int idx = t; idx < BM * 8; idx += THREADS) {
        int r = idx >> 3, q = idx & 7;
        float4 v = *(const float4*)&z[(size_t)(rowbase + r) * 64 + 32 + q * 4];
        *(float4*)&As[r * AS_STRIDE + q * 4] = v;
    }
    // A tile: c part (cols 32..47)
    for (int idx = t; idx < BM * 4; idx += THREADS) {
        int r = idx >> 2, q = idx & 3;
        float4 v = *(const float4*)&c[(size_t)(rowbase + r) * 16 + q * 4];
        *(float4*)&As[r * AS_STRIDE + 32 + q * 4] = v;
    }
    __syncthreads();

    const int ln = t & 7;            // local group in [0,8)
    const int rs = t >> 3;           // row slot in [0,64)
    const int r0 = rs * 2, r1 = r0 + 1;
    const int gn = g * NGRP + ln;    // global spline index in [0,32)

    const float* wcol = Ws + ln * NPAD;
    const unsigned long long* b2 = (const unsigned long long*)(bs + ln * NPAD);

    unsigned long long acc0[17], acc1[17];
#pragma unroll
    for (int p = 0; p < 17; p++) { acc0[p] = b2[p]; acc1[p] = b2[p]; }

#pragma unroll 4
    for (int k = 0; k < KDIM; k++) {
        float a0 = As[r0 * AS_STRIDE + k];
        float a1 = As[r1 * AS_STRIDE + k];
        unsigned long long ap0 = pack2(a0);
        unsigned long long ap1 = pack2(a1);
        const unsigned long long* w2 = (const unsigned long long*)(wcol + k * WS_STRIDE);
#pragma unroll
        for (int p = 0; p < 17; p++) {
            unsigned long long wv = w2[p];
            ffma2(acc0[p], ap0, wv);
            ffma2(acc1[p], ap1, wv);
        }
    }

    // spline + outputs
    const int row0 = rowbase + r0;
    const int row1 = rowbase + r1;
    float x0, x1v;
    float ld0 = spline_eval(acc0, z[(size_t)row0 * 64 + gn], x0);
    float ld1 = spline_eval(acc1, z[(size_t)row1 * 64 + gn], x1v);
    out[(size_t)row0 * 64 + 32 + gn] = x0;
    out[(size_t)row1 * 64 + 32 + gn] = x1v;

    // reduce log_det over the 8 n-lanes of this group (lanes are consecutive)
    ld0 += __shfl_xor_sync(0xffffffffu, ld0, 1);
    ld0 += __shfl_xor_sync(0xffffffffu, ld0, 2);
    ld0 += __shfl_xor_sync(0xffffffffu, ld0, 4);
    ld1 += __shfl_xor_sync(0xffffffffu, ld1, 1);
    ld1 += __shfl_xor_sync(0xffffffffu, ld1, 2);
    ld1 += __shfl_xor_sync(0xffffffffu, ld1, 4);
    if (ln == 0) {
        atomicAdd(&out[(size_t)MROWS * 64 + row0], ld0);
        atomicAdd(&out[(size_t)MROWS * 64 + row1], ld1);
    }
}

extern "C" void kernel_launch(void* const* d_in, const int* in_sizes, int n_in,
                              void* d_out, int out_size) {
    const float* c = (const float*)d_in[0];   // (65536, 16)
    const float* z = (const float*)d_in[1];   // (65536, 64)
    const float* W = (const float*)d_in[2];   // (48, 1056)
    const float* b = (const float*)d_in[3];   // (1056,)
    float* out = (float*)d_out;               // 65536*64 (x) + 65536 (log_det)

    cudaFuncSetAttribute(spline_main_kernel,
                         cudaFuncAttributeMaxDynamicSharedMemorySize, SMEM_BYTES);

    int total = MROWS * 8 + MROWS / 4;
    prep_kernel<<<(total + 255) / 256, 256>>>(z, out);

    dim3 grid(NSPL / NGRP, MROWS / BM);       // (4, 512)
    spline_main_kernel<<<grid, THREADS, SMEM_BYTES>>>(c, z, W, b, out);
}

// round 3
// speedup vs baseline: 1.0038x; 1.0038x over previous
#include <cuda_runtime.h>
#include <cstdint>

// Problem constants
#define MROWS   65536
#define KDIM    48          // s_in = 32 + 16
#define NSPL    32          // spline groups per row
#define NB      33          // 2K+1 outputs per group (17 heights, 16 widths)
#define NPAD    34          // padded group width (even, for LDS.64)
#define NGRP    8           // spline groups per block
#define BM      128         // rows per block
#define TM      2           // rows per thread
#define THREADS 512         // (BM/TM) * NGRP
#define WS_STRIDE (NGRP * NPAD)                 // 272 floats per k-row
#define AS_STRIDE 52                            // padded A row (mult of 4, conflict-free)
#define SMEM_FLOATS (KDIM * WS_STRIDE + BM * AS_STRIDE + WS_STRIDE)
#define SMEM_BYTES  (SMEM_FLOATS * 4)           // 79936 B

// ---------- packed f32x2 helpers ----------
__device__ __forceinline__ unsigned long long pack2(float a) {
    unsigned long long r;
    asm("mov.b64 %0, {%1, %1};" : "=l"(r) : "f"(a));
    return r;
}
__device__ __forceinline__ void ffma2(unsigned long long& d,
                                      unsigned long long a,
                                      unsigned long long b) {
    asm("fma.rn.f32x2 %0, %1, %2, %0;" : "+l"(d) : "l"(a), "l"(b));
}

// ---------- quadratic spline (per (m,n) pair) ----------
// y[0..16] = unnormalized heights, y[17..32] = unnormalized widths
__device__ __forceinline__ float spline_eval(const unsigned long long acc[17],
                                             float input, float& x_out) {
    float y[34];
#pragma unroll
    for (int p = 0; p < 17; p++) {
        unsigned int lo = (unsigned int)acc[p];
        unsigned int hi = (unsigned int)(acc[p] >> 32);
        y[2 * p]     = __uint_as_float(lo);
        y[2 * p + 1] = __uint_as_float(hi);
    }

    // h = softplus(uh) + 0.001  (robust softplus, matches jax.nn.softplus)
    float h[17];
#pragma unroll
    for (int i = 0; i < 17; i++) {
        float x = y[i];
        h[i] = fmaxf(x, 0.0f) + log1pf(expf(-fabsf(x))) + 0.001f;
    }

    // widths = MIN_BW + (1 - 16*MIN_BW) * softmax(uw)
    float w[16];
    float esum = 0.0f;
#pragma unroll
    for (int i = 0; i < 16; i++) { w[i] = expf(y[17 + i]); esum += w[i]; }
    float inv = 1.0f / esum;
#pragma unroll
    for (int i = 0; i < 16; i++) w[i] = 0.001f + 0.984f * (w[i] * inv);

    // area & normalized heights
    float area = 0.0f;
#pragma unroll
    for (int i = 0; i < 16; i++) area += (h[i] + h[i + 1]) * 0.5f * w[i];
    float hs = 0.999f / area;   // (1 - MIN_BH)/area
#pragma unroll
    for (int i = 0; i < 17; i++) h[i] = 0.001f + h[i] * hs;

    // sequential scan: locations / left-cdf cumsums + predicated bin select.
    // bin_locations[i] = sum_{j<i} w_j (i<=15); index 16 forced to 1+eps > input.
    float L = 0.0f, C = 0.0f;
    float bl = 0.0f, bw = w[0], lcdf = 0.0f, hl = h[0], hr = h[1];
#pragma unroll
    for (int i = 1; i <= 15; i++) {
        L += w[i - 1];
        C += 0.5f * (h[i - 1] + h[i]) * w[i - 1];
        if (input >= L) { bl = L; bw = w[i]; lcdf = C; hl = h[i]; hr = h[i + 1]; }
    }

    float aq    = 0.5f * (hr - hl) * bw;
    float bq    = hl * bw;
    float alpha = (input - bl) / bw;
    float o = aq * alpha * alpha + bq * alpha + lcdf;
    x_out = fminf(fmaxf(o, 0.0f), 1.0f);
    return logf(alpha * (hr - hl) + hl);
}

// ---------- prep: copy z2 into x[:, :32], zero log_det ----------
__global__ void prep_kernel(const float* __restrict__ z, float* __restrict__ out) {
    int tid = blockIdx.x * blockDim.x + threadIdx.x;
    const int NC = MROWS * 8;                  // float4 copies for x[:, :32]
    if (tid < NC) {
        int m = tid >> 3, q = tid & 7;
        ((float4*)out)[(size_t)m * 16 + q] = ((const float4*)z)[(size_t)m * 16 + 8 + q];
    } else {
        int u = tid - NC;
        if (u < MROWS / 4) {
            ((float4*)(out + (size_t)MROWS * 64))[u] = make_float4(0.f, 0.f, 0.f, 0.f);
        }
    }
}

// ---------- fused GEMM + spline ----------
__global__ void __launch_bounds__(THREADS, 1)
spline_main_kernel(const float* __restrict__ c, const float* __restrict__ z,
                   const float* __restrict__ W, const float* __restrict__ b,
                   float* __restrict__ out) {
    extern __shared__ float sm[];
    float* Ws = sm;                                   // [48][272]  W slice (padded)
    float* As = sm + KDIM * WS_STRIDE;                // [128][52]  A tile
    float* bs = As + BM * AS_STRIDE;                  // [272]      bias slice

    const int t       = threadIdx.x;
    const int g       = blockIdx.x;                   // n-group (0..3)
    const int rowbase = blockIdx.y * BM;

    // W slice: cols [g*264, g*264+264), laid out Ws[k*272 + ln*34 + j]
    for (int idx = t; idx < KDIM * (NGRP * NB); idx += THREADS) {
        int k  = idx / (NGRP * NB);
        int cc = idx - k * (NGRP * NB);
        int ln = cc / NB;
        int j  = cc - ln * NB;
        Ws[k * WS_STRIDE + ln * NPAD + j] = W[(size_t)k * 1056 + g * (NGRP * NB) + cc];
    }
    for (int idx = t; idx < KDIM * NGRP; idx += THREADS) {  // zero pad column j=33
        int k = idx >> 3, ln = idx & 7;
        Ws[k * WS_STRIDE + ln * NPAD + 33] = 0.0f;
    }
    if (t < WS_STRIDE) {                                    // bias (padded)
        int ln = t / NPAD, j = t - ln * NPAD;
        bs[t] = (j < NB) ? b[g * (NGRP * NB) + ln * NB + j] : 0.0f;
    }
    // A tile: z2 part (cols 0..31 of A = z[:,32:64])
    for (int idx = t; idx < BM * 8; idx += THREADS) {
        int r = idx >> 3, q = idx & 7;
        float4 v = *(const float4*)&z[(size_t)(rowbase + r) * 64 + 32 + q * 4];
        *(float4*)&As[r * AS_STRIDE + q * 4] = v;
    }
    // A tile: c part (cols 32..47)
    for (int idx = t; idx < BM * 4; idx += THREADS) {
        int r = idx >> 2, q = idx & 3;
        float4 v = *(const float4*)&c[(size_t)(rowbase + r) * 16 + q * 4];
        *(float4*)&As[r * AS_STRIDE + 32 + q * 4] = v;
    }
    __syncthreads();

    const int ln = t & 7;            // local group in [0,8)
    const int rs = t >> 3;           // row slot in [0,64)
    const int r0 = rs * 2, r1 = r0 + 1;
    const int gn = g * NGRP + ln;    // global spline index in [0,32)

    const float* wcol = Ws + ln * NPAD;
    const unsigned long long* b2 = (const unsigned long long*)(bs + ln * NPAD);

    unsigned long long acc0[17], acc1[17];
#pragma unroll
    for (int p = 0; p < 17; p++) { acc0[p] = b2[p]; acc1[p] = b2[p]; }

#pragma unroll 4
    for (int k = 0; k < KDIM; k++) {
        float a0 = As[r0 * AS_STRIDE + k];
        float a1 = As[r1 * AS_STRIDE + k];
        unsigned long long ap0 = pack2(a0);
        unsigned long long ap1 = pack2(a1);
        const unsigned long long* w2 = (const unsigned long long*)(wcol + k * WS_STRIDE);
#pragma unroll
        for (int p = 0; p < 17; p++) {
            unsigned long long wv = w2[p];
            ffma2(acc0[p], ap0, wv);
            ffma2(acc1[p], ap1, wv);
        }
    }

    // spline + outputs
    const int row0 = rowbase + r0;
    const int row1 = rowbase + r1;
    float x0, x1v;
    float ld0 = spline_eval(acc0, z[(size_t)row0 * 64 + gn], x0);
    float ld1 = spline_eval(acc1, z[(size_t)row1 * 64 + gn], x1v);
    out[(size_t)row0 * 64 + 32 + gn] = x0;
    out[(size_t)row1 * 64 + 32 + gn] = x1v;

    // reduce log_det over the 8 n-lanes of this group (lanes are consecutive)
    ld0 += __shfl_xor_sync(0xffffffffu, ld0, 1);
    ld0 += __shfl_xor_sync(0xffffffffu, ld0, 2);
    ld0 += __shfl_xor_sync(0xffffffffu, ld0, 4);
    ld1 += __shfl_xor_sync(0xffffffffu, ld1, 1);
    ld1 += __shfl_xor_sync(0xffffffffu, ld1, 2);
    ld1 += __shfl_xor_sync(0xffffffffu, ld1, 4);
    if (ln == 0) {
        atomicAdd(&out[(size_t)MROWS * 64 + row0], ld0);
        atomicAdd(&out[(size_t)MROWS * 64 + row1], ld1);
    }
}

extern "C" void kernel_launch(void* const* d_in, const int* in_sizes, int n_in,
                              void* d_out, int out_size) {
    const float* c = (const float*)d_in[0];   // (65536, 16)
    const float* z = (const float*)d_in[1];   // (65536, 64)
    const float* W = (const float*)d_in[2];   // (48, 1056)
    const float* b = (const float*)d_in[3];   // (1056,)
    float* out = (float*)d_out;               // 65536*64 (x) + 65536 (log_det)

    cudaFuncSetAttribute(spline_main_kernel,
                         cudaFuncAttributeMaxDynamicSharedMemorySize, SMEM_BYTES);

    int total = MROWS * 8 + MROWS / 4;
    prep_kernel<<<(total + 255) / 256, 256>>>(z, out);

    dim3 grid(NSPL / NGRP, MROWS / BM);       // (4, 512)
    spline_main_kernel<<<grid, THREADS, SMEM_BYTES>>>(c, z, W, b, out);
}